// round 1
// baseline (speedup 1.0000x reference)
#include <cuda_runtime.h>
#include <cuda_bf16.h>
#include <math.h>

// Problem constants
#define Dq   1024
#define Hh   16
#define HDq  64
#define Bq   2
#define Nq   1024
#define ROWS (Bq * Nq)          // 2048
#define OUT_FINAL (ROWS * Dq)   // 2097152

// Scratch (device globals — no allocation allowed)
__device__ float g_hf[ROWS * Dq];     // head_features, layout [b*N+n][h*64+e]
__device__ float g_multi[ROWS * Dq];  // fused head outputs, same layout
__device__ float g_mu[Bq * Dq];       // column means of g_hf per batch
__device__ float g_beff[Hh * Bq * HDq];

// ---------------------------------------------------------------------------
// Generic fp32 GEMM: C[M,Nt] = A[M,K] @ B[Nt,K]^T   (both operands K-major)
// BM=128, BN=64, BK=16, TM=8, TN=4, 256 threads. M,Nt,K divisible by tiles.
// ---------------------------------------------------------------------------
#define BM 128
#define BN 64
#define BK 16
#define TM 8
#define TN 4

__global__ void __launch_bounds__(256, 2)
gemm_nt(const float* __restrict__ A, const float* __restrict__ B,
        float* __restrict__ C, int M, int Nt, int K) {
    __shared__ float As[BK][BM];
    __shared__ float Bs[BK][BN];

    const int tid = threadIdx.x;
    const int bm = blockIdx.y * BM;
    const int bn = blockIdx.x * BN;

    const int lrow = tid >> 2;           // 0..63
    const int lcol = (tid & 3) << 2;     // 0,4,8,12

    const int tr = (tid >> 4) * TM;      // 0..120 step 8
    const int tc = (tid & 15) * TN;      // 0..60 step 4

    float acc[TM][TN];
#pragma unroll
    for (int j = 0; j < TM; j++)
#pragma unroll
        for (int i = 0; i < TN; i++) acc[j][i] = 0.0f;

    for (int k0 = 0; k0 < K; k0 += BK) {
        // Load A tile 128x16 (512 float4, 2 per thread), store transposed
#pragma unroll
        for (int it = 0; it < 2; it++) {
            int r = lrow + 64 * it;
            float4 v = *(const float4*)&A[(size_t)(bm + r) * K + k0 + lcol];
            As[lcol + 0][r] = v.x;
            As[lcol + 1][r] = v.y;
            As[lcol + 2][r] = v.z;
            As[lcol + 3][r] = v.w;
        }
        // Load B tile 64x16 (256 float4, 1 per thread), store transposed
        {
            float4 v = *(const float4*)&B[(size_t)(bn + lrow) * K + k0 + lcol];
            Bs[lcol + 0][lrow] = v.x;
            Bs[lcol + 1][lrow] = v.y;
            Bs[lcol + 2][lrow] = v.z;
            Bs[lcol + 3][lrow] = v.w;
        }
        __syncthreads();

#pragma unroll
        for (int k = 0; k < BK; k++) {
            float a[TM], b[TN];
            float4 a0 = *(const float4*)&As[k][tr];
            float4 a1 = *(const float4*)&As[k][tr + 4];
            a[0] = a0.x; a[1] = a0.y; a[2] = a0.z; a[3] = a0.w;
            a[4] = a1.x; a[5] = a1.y; a[6] = a1.z; a[7] = a1.w;
            float4 b0 = *(const float4*)&Bs[k][tc];
            b[0] = b0.x; b[1] = b0.y; b[2] = b0.z; b[3] = b0.w;
#pragma unroll
            for (int j = 0; j < TM; j++)
#pragma unroll
                for (int i = 0; i < TN; i++)
                    acc[j][i] = fmaf(a[j], b[i], acc[j][i]);
        }
        __syncthreads();
    }

#pragma unroll
    for (int j = 0; j < TM; j++) {
        float4 v = make_float4(acc[j][0], acc[j][1], acc[j][2], acc[j][3]);
        *(float4*)&C[(size_t)(bm + tr + j) * Nt + bn + tc] = v;
    }
}

// ---------------------------------------------------------------------------
// Column mean of g_hf per batch: g_mu[b][c] = mean_n g_hf[b*N+n][c]
// ---------------------------------------------------------------------------
__global__ void mu_kernel() {
    int gid = blockIdx.x * 256 + threadIdx.x;   // 0..2047
    int b = gid >> 10;
    int c = gid & 1023;
    const float* p = g_hf + (size_t)b * Nq * Dq + c;
    float s = 0.0f;
    for (int n = 0; n < Nq; n++) s += p[(size_t)n * Dq];
    g_mu[b * Dq + c] = s * (1.0f / (float)Nq);
}

// ---------------------------------------------------------------------------
// Effective bias: beff[h,b,e] = fu_b1[h,e] + sum_e' (W1b+W1c)[h,e,e'] * mu[b,h*64+e']
// ---------------------------------------------------------------------------
__global__ void beff_kernel(const float* __restrict__ fu_W1,
                            const float* __restrict__ fu_b1) {
    int hb = blockIdx.x;            // 0..31
    int h = hb >> 1, b = hb & 1;
    int e = threadIdx.x;            // 0..63
    const float* w = fu_W1 + (size_t)h * HDq * 3 * HDq + (size_t)e * 3 * HDq;
    const float* mu = g_mu + b * Dq + h * HDq;
    float acc = fu_b1[h * HDq + e];
    for (int ep = 0; ep < HDq; ep++)
        acc = fmaf(w[HDq + ep] + w[2 * HDq + ep], mu[ep], acc);
    g_beff[(hb)*HDq + e] = acc;
}

// ---------------------------------------------------------------------------
// Fusion MLP per (h,b,n): x = GELU(W1a@hf + beff); y = W2@x + b2 -> g_multi
// Block = 256 threads, handles 128 consecutive n rows (4 at a time).
// Grid = (N/128, B, H)
// ---------------------------------------------------------------------------
__global__ void __launch_bounds__(256)
fusion_kernel(const float* __restrict__ fu_W1, const float* __restrict__ fu_W2,
              const float* __restrict__ fu_b2) {
    __shared__ float W1T[HDq * HDq];   // W1T[e'][e]
    __shared__ float W2T[HDq * HDq];   // W2T[e][f]
    __shared__ float be[HDq], b2[HDq];
    __shared__ float hrow[4][HDq];
    __shared__ float xbuf[4][HDq];

    const int h = blockIdx.z, b = blockIdx.y;
    const int n0 = blockIdx.x * 128;
    const int tid = threadIdx.x;

    // Load transposed weights (coalesced gmem reads)
#pragma unroll
    for (int it = 0; it < 16; it++) {
        int er = it * 4 + (tid >> 6);   // output row index
        int ec = tid & 63;              // input col index
        W1T[ec * HDq + er] = fu_W1[(size_t)h * HDq * 3 * HDq + (size_t)er * 3 * HDq + ec];
        W2T[ec * HDq + er] = fu_W2[(size_t)h * HDq * HDq + (size_t)er * HDq + ec];
    }
    if (tid < HDq) {
        be[tid] = g_beff[(h * 2 + b) * HDq + tid];
        b2[tid] = fu_b2[h * HDq + tid];
    }
    __syncthreads();

    const int g = tid >> 6;       // group 0..3 (one n-row each)
    const int e = tid & 63;

    for (int r0 = 0; r0 < 128; r0 += 4) {
        int n = n0 + r0 + g;
        size_t row = (size_t)(b * Nq + n) * Dq + h * HDq;
        hrow[g][e] = g_hf[row + e];
        __syncthreads();

        float acc = be[e];
#pragma unroll
        for (int ep = 0; ep < HDq; ep++)
            acc = fmaf(W1T[ep * HDq + e], hrow[g][ep], acc);
        // exact GELU
        float x = 0.5f * acc * (1.0f + erff(acc * 0.70710678118654752f));
        xbuf[g][e] = x;
        __syncthreads();

        float acc2 = b2[e];
#pragma unroll
        for (int ep = 0; ep < HDq; ep++)
            acc2 = fmaf(W2T[ep * HDq + e], xbuf[g][ep], acc2);
        g_multi[row + e] = acc2;
        __syncthreads();
    }
}

// ---------------------------------------------------------------------------
// Tail: fwd_targets[0], bwd_targets[0], avg_strength
// ---------------------------------------------------------------------------
__global__ void tail_kernel(const int* __restrict__ prev_idx,
                            const float* __restrict__ chain_ratio,
                            float* __restrict__ out) {
    int idx = blockIdx.x * 256 + threadIdx.x;   // 0..2047
    if (idx >= ROWS) return;
    int n = idx & (Nq - 1);

    float cr = *chain_ratio;
    float thr = floorf((float)Nq / (1.0f + expf(-cr)));   // floor(sigmoid*N)

    int p = prev_idx[idx];
    p = min(max(p, 0), Nq - 1);

    // uniform softmax -> E[pos] = (N-1)/2 = 511.5 -> int32 trunc = 511
    float ft = ((float)n >= thr) ? (float)p : 511.0f;
    out[OUT_FINAL + idx] = ft;
    out[OUT_FINAL + ROWS + idx] = 511.0f;

    float s = 1.0f - logf(1.0f / (float)Nq + 1e-8f);
    out[OUT_FINAL + 2 * ROWS + idx] = s;
}

// ---------------------------------------------------------------------------
extern "C" void kernel_launch(void* const* d_in, const int* in_sizes, int n_in,
                              void* d_out, int out_size) {
    const float* h_in     = (const float*)d_in[0];
    const int*   prev_idx = (const int*)d_in[1];
    // d_in[2..9] = fw/bw encoder weights: provably dead (softmax of broadcast
    // scalar logit is uniform), never read.
    const float* Wv    = (const float*)d_in[10];  // [H,HD,D] == [1024,1024]
    const float* fu_W1 = (const float*)d_in[11];
    const float* fu_b1 = (const float*)d_in[12];
    const float* fu_W2 = (const float*)d_in[13];
    const float* fu_b2 = (const float*)d_in[14];
    const float* Wo    = (const float*)d_in[15];  // [D,D]
    const float* chain_ratio = (const float*)d_in[16];
    float* out = (float*)d_out;

    float* hf;    cudaGetSymbolAddress((void**)&hf, g_hf);
    float* multi; cudaGetSymbolAddress((void**)&multi, g_multi);

    dim3 gemm_grid(Dq / BN, ROWS / BM);   // (16,16)

    // 1) head_features: [2048,1024] = h @ Wv_flat^T
    gemm_nt<<<gemm_grid, 256>>>(h_in, Wv, hf, ROWS, Dq, Dq);

    // 2) per-batch column means (fwd_feats == bwd_feats == mu)
    mu_kernel<<<(Bq * Dq) / 256, 256>>>();

    // 3) effective first-layer bias
    beff_kernel<<<Hh * Bq, HDq>>>(fu_W1, fu_b1);

    // 4) fusion MLP -> g_multi
    fusion_kernel<<<dim3(Nq / 128, Bq, Hh), 256>>>(fu_W1, fu_W2, fu_b2);

    // 5) final output GEMM: out[0:2097152] = multi @ Wo^T
    gemm_nt<<<gemm_grid, 256>>>(multi, Wo, out, ROWS, Dq, Dq);

    // 6) targets + strength tail
    tail_kernel<<<ROWS / 256, 256>>>(prev_idx, chain_ratio, out);
}

// round 5
// speedup vs baseline: 2.7391x; 2.7391x over previous
#include <cuda_runtime.h>
#include <cuda_bf16.h>
#include <math.h>
#include <stdint.h>

// Problem constants
#define Dq   1024
#define Hh   16
#define HDq  64
#define Bq   2
#define Nq   1024
#define ROWS (Bq * Nq)          // 2048
#define OUT_FINAL (ROWS * Dq)   // 2097152

// ---------------------------------------------------------------------------
// Scratch (device globals — no allocation allowed)
// ---------------------------------------------------------------------------
__device__ float g_hf[ROWS * Dq];                 // head_features fp32
__device__ float g_mu[Bq * Dq];                   // column SUMS of g_hf per batch
__device__ float g_beff[Hh * Bq * HDq];
__device__ __nv_bfloat16 g_Ah[ROWS * Dq], g_Al[ROWS * Dq];    // h split
__device__ __nv_bfloat16 g_WvH[Dq * Dq], g_WvL[Dq * Dq];      // Wv split
__device__ __nv_bfloat16 g_WoH[Dq * Dq], g_WoL[Dq * Dq];      // Wo split
__device__ __nv_bfloat16 g_mH[ROWS * Dq], g_mL[ROWS * Dq];    // multi split

// ---------------------------------------------------------------------------
// Helpers (base-target instructions only: ldmatrix / mma.sync / cp.async)
// ---------------------------------------------------------------------------
__device__ __forceinline__ uint32_t smem_u32(const void* p) {
    uint32_t a;
    asm("{ .reg .u64 t; cvta.to.shared.u64 t, %1; cvt.u32.u64 %0, t; }"
        : "=r"(a) : "l"(p));
    return a;
}
#define SW128(o) ((o) ^ (((o) >> 3) & 0x70))

#define CP_ASYNC16(dst, src) \
    asm volatile("cp.async.cg.shared.global [%0], [%1], 16;" :: "r"(dst), "l"(src))
#define CP_COMMIT() asm volatile("cp.async.commit_group;")
#define CP_WAIT0()  asm volatile("cp.async.wait_group 0;" ::: "memory")

__device__ __forceinline__ void ldsm_x4(uint32_t* r, uint32_t addr) {
    asm volatile("ldmatrix.sync.aligned.m8n8.x4.shared.b16 {%0,%1,%2,%3}, [%4];"
                 : "=r"(r[0]), "=r"(r[1]), "=r"(r[2]), "=r"(r[3]) : "r"(addr));
}

__device__ __forceinline__ void mma16816(float* c, const uint32_t* a, const uint32_t* b) {
    asm volatile(
        "mma.sync.aligned.m16n8k16.row.col.f32.bf16.bf16.f32 "
        "{%0,%1,%2,%3}, {%4,%5,%6,%7}, {%8,%9}, {%0,%1,%2,%3};"
        : "+f"(c[0]), "+f"(c[1]), "+f"(c[2]), "+f"(c[3])
        : "r"(a[0]), "r"(a[1]), "r"(a[2]), "r"(a[3]), "r"(b[0]), "r"(b[1]));
}

// ---------------------------------------------------------------------------
// fp32 -> bf16 hi/lo split (vectorized float4). Also zeroes g_mu when zmu!=0.
// ---------------------------------------------------------------------------
__global__ void cvt_hilo(const float4* __restrict__ x, __nv_bfloat16* __restrict__ hi,
                         __nv_bfloat16* __restrict__ lo, int n4, int zmu) {
    int i = blockIdx.x * 256 + threadIdx.x;
    if (zmu && i < (Bq * Dq) / 4) ((float4*)g_mu)[i] = make_float4(0.f, 0.f, 0.f, 0.f);
    if (i >= n4) return;
    float4 v = x[i];
    __nv_bfloat16 h0 = __float2bfloat16(v.x);
    __nv_bfloat16 h1 = __float2bfloat16(v.y);
    __nv_bfloat16 h2 = __float2bfloat16(v.z);
    __nv_bfloat16 h3 = __float2bfloat16(v.w);
    __nv_bfloat16 l0 = __float2bfloat16(v.x - __bfloat162float(h0));
    __nv_bfloat16 l1 = __float2bfloat16(v.y - __bfloat162float(h1));
    __nv_bfloat16 l2 = __float2bfloat16(v.z - __bfloat162float(h2));
    __nv_bfloat16 l3 = __float2bfloat16(v.w - __bfloat162float(h3));
    __nv_bfloat162 p;
    p.x = h0; p.y = h1; ((__nv_bfloat162*)hi)[i * 2] = p;
    p.x = h2; p.y = h3; ((__nv_bfloat162*)hi)[i * 2 + 1] = p;
    p.x = l0; p.y = l1; ((__nv_bfloat162*)lo)[i * 2] = p;
    p.x = l2; p.y = l3; ((__nv_bfloat162*)lo)[i * 2 + 1] = p;
}

// ---------------------------------------------------------------------------
// HMMA bf16 split GEMM: C[2048,1024] f32 = (Ah+Al)[2048,1024] @ (Bh+Bl)^T
// Folded as one K'=3072 GEMM over segments (Ah,Bh),(Al,Bh),(Ah,Bl).
// Tile 128x128, BK=64 bf16 (128B rows, SW128). 256 thr, 8 warps (4m x 2n),
// warp tile 32x64, mma.sync m16n8k16, cp.async double buffered.
// ---------------------------------------------------------------------------
#define G_STAGE 32768            // A 16KB + B 16KB per stage
#define G_SMEM  (2 * G_STAGE)    // 64KB

__device__ __forceinline__ void load_tile(uint32_t sA, uint32_t sB,
                                          const __nv_bfloat16* __restrict__ Aseg,
                                          const __nv_bfloat16* __restrict__ Bseg,
                                          int bm, int bn, int kin, int tid) {
#pragma unroll
    for (int rep = 0; rep < 4; rep++) {
        int id = rep * 256 + tid;        // 0..1023
        int row = id >> 3, c = id & 7;   // 128 rows x 8 chunks of 16B
        uint32_t so = SW128((uint32_t)(row * 128 + c * 16));
        const __nv_bfloat16* ga = Aseg + (size_t)(bm + row) * Dq + kin + c * 8;
        const __nv_bfloat16* gb = Bseg + (size_t)(bn + row) * Dq + kin + c * 8;
        CP_ASYNC16(sA + so, ga);
        CP_ASYNC16(sB + so, gb);
    }
}

__global__ void __launch_bounds__(256, 1)
gemm_hmma(const __nv_bfloat16* __restrict__ Ah, const __nv_bfloat16* __restrict__ Al,
          const __nv_bfloat16* __restrict__ Bh, const __nv_bfloat16* __restrict__ Bl,
          float* __restrict__ C) {
    extern __shared__ char sm[];
    const uint32_t smb = smem_u32(sm);
    const int tid = threadIdx.x;
    const int warp = tid >> 5, lane = tid & 31;
    const int wm = warp >> 1, wn = warp & 1;
    const int bm = blockIdx.y * 128, bn = blockIdx.x * 128;

    const __nv_bfloat16* Asegs[3] = {Ah, Al, Ah};
    const __nv_bfloat16* Bsegs[3] = {Bh, Bh, Bl};

    float acc[2][8][4];
#pragma unroll
    for (int mt = 0; mt < 2; mt++)
#pragma unroll
        for (int nt = 0; nt < 8; nt++)
#pragma unroll
            for (int i = 0; i < 4; i++) acc[mt][nt][i] = 0.0f;

    // Precompute ldmatrix smem offsets (within a tile)
    uint32_t a_off[2], b_off[4];
#pragma unroll
    for (int mt = 0; mt < 2; mt++) {
        int row = wm * 32 + mt * 16 + (lane & 15);
        a_off[mt] = (uint32_t)(row * 128 + (lane >> 4) * 16);
    }
#pragma unroll
    for (int np = 0; np < 4; np++) {
        int n = wn * 64 + np * 16 + (lane >> 4) * 8 + (lane & 7);
        b_off[np] = (uint32_t)(n * 128 + ((lane >> 3) & 1) * 16);
    }

    // Prologue
    load_tile(smb, smb + 16384, Asegs[0], Bsegs[0], bm, bn, 0, tid);
    CP_COMMIT();

    for (int kt = 0; kt < 48; kt++) {
        CP_WAIT0();
        __syncthreads();
        const int buf = kt & 1;
        if (kt + 1 < 48) {
            int s = (kt + 1) >> 4;
            int kin = ((kt + 1) & 15) * 64;
            load_tile(smb + (buf ^ 1) * G_STAGE, smb + (buf ^ 1) * G_STAGE + 16384,
                      Asegs[s], Bsegs[s], bm, bn, kin, tid);
            CP_COMMIT();
        }
        const uint32_t sA = smb + buf * G_STAGE;
        const uint32_t sB = sA + 16384;
#pragma unroll
        for (int ks = 0; ks < 4; ks++) {
            uint32_t af[2][4], bf[8][2];
#pragma unroll
            for (int mt = 0; mt < 2; mt++)
                ldsm_x4(af[mt], sA + SW128(a_off[mt] + ks * 32));
#pragma unroll
            for (int np = 0; np < 4; np++) {
                uint32_t r[4];
                ldsm_x4(r, sB + SW128(b_off[np] + ks * 32));
                bf[np * 2][0] = r[0]; bf[np * 2][1] = r[1];
                bf[np * 2 + 1][0] = r[2]; bf[np * 2 + 1][1] = r[3];
            }
#pragma unroll
            for (int mt = 0; mt < 2; mt++)
#pragma unroll
                for (int nt = 0; nt < 8; nt++)
                    mma16816(acc[mt][nt], af[mt], bf[nt]);
        }
    }

    // Epilogue: direct f32 stores
#pragma unroll
    for (int mt = 0; mt < 2; mt++) {
        int row = bm + wm * 32 + mt * 16 + (lane >> 2);
#pragma unroll
        for (int nt = 0; nt < 8; nt++) {
            int col = bn + wn * 64 + nt * 8 + (lane & 3) * 2;
            *(float2*)&C[(size_t)row * Dq + col] =
                make_float2(acc[mt][nt][0], acc[mt][nt][1]);
            *(float2*)&C[(size_t)(row + 8) * Dq + col] =
                make_float2(acc[mt][nt][2], acc[mt][nt][3]);
        }
    }
}

// ---------------------------------------------------------------------------
// Column sums of g_hf per batch (atomicAdd into g_mu, pre-zeroed)
// ---------------------------------------------------------------------------
__global__ void mu_sum() {
    const int b = blockIdx.y, chunk = blockIdx.x, tid = threadIdx.x;
    const float* base = g_hf + ((size_t)b * Nq + chunk * 64) * Dq + tid * 4;
    float4 s = make_float4(0.f, 0.f, 0.f, 0.f);
#pragma unroll 4
    for (int r = 0; r < 64; r++) {
        float4 v = *(const float4*)(base + (size_t)r * Dq);
        s.x += v.x; s.y += v.y; s.z += v.z; s.w += v.w;
    }
    float* m = &g_mu[b * Dq + tid * 4];
    atomicAdd(m + 0, s.x); atomicAdd(m + 1, s.y);
    atomicAdd(m + 2, s.z); atomicAdd(m + 3, s.w);
}

// ---------------------------------------------------------------------------
// Effective bias: beff[h,b,e] = fu_b1[h,e] + sum_e' (W1b+W1c)[h,e,e'] * mu/N
// ---------------------------------------------------------------------------
__global__ void beff_kernel(const float* __restrict__ fu_W1,
                            const float* __restrict__ fu_b1) {
    int hb = blockIdx.x;            // 0..31
    int h = hb >> 1, b = hb & 1;
    int e = threadIdx.x;            // 0..63
    const float* w = fu_W1 + (size_t)h * HDq * 3 * HDq + (size_t)e * 3 * HDq;
    const float* mu = g_mu + b * Dq + h * HDq;
    float acc = fu_b1[h * HDq + e];
    const float inv = 1.0f / (float)Nq;
#pragma unroll 8
    for (int ep = 0; ep < HDq; ep++)
        acc = fmaf(w[HDq + ep] + w[2 * HDq + ep], mu[ep] * inv, acc);
    g_beff[hb * HDq + e] = acc;
}

// ---------------------------------------------------------------------------
// Fusion MLP, register-tiled. 128 rows x 64 cols per (rowchunk, head).
// Grid (16, 16), 256 threads, TM=8 x TN=4. Outputs multi as bf16 hi/lo.
// ---------------------------------------------------------------------------
#define F_HFS 0
#define F_W1S (64 * 132)
#define F_W2S (64 * 132 + 64 * 68)
#define F_SMEM ((64 * 132 + 2 * 64 * 68) * 4)

__global__ void __launch_bounds__(256)
fusion_kernel(const float* __restrict__ fu_W1, const float* __restrict__ fu_W2,
              const float* __restrict__ fu_b2) {
    extern __shared__ float fsm[];
    float* HFs = fsm + F_HFS;
    float* W1s = fsm + F_W1S;
    float* W2s = fsm + F_W2S;

    const int rc = blockIdx.x, h = blockIdx.y;
    const int b = rc >> 3;
    const int tid = threadIdx.x;
    const int tr = (tid >> 4) * 8;     // 0..120
    const int tc = (tid & 15) * 4;     // 0..60
    const size_t rowbase = (size_t)rc * 128;

    // HF tile transposed (k-major): HFs[c][r]
#pragma unroll
    for (int rep = 0; rep < 8; rep++) {
        int e = rep * 256 + tid;
        int r = e >> 4, c4 = (e & 15) * 4;
        float4 v = *(const float4*)&g_hf[(rowbase + r) * Dq + h * HDq + c4];
        HFs[(c4 + 0) * 132 + r] = v.x;
        HFs[(c4 + 1) * 132 + r] = v.y;
        HFs[(c4 + 2) * 132 + r] = v.z;
        HFs[(c4 + 3) * 132 + r] = v.w;
    }
#pragma unroll
    for (int rep = 0; rep < 16; rep++) {
        int idx = rep * 256 + tid;
        int e = idx >> 6, c = idx & 63;
        W1s[c * 68 + e] = fu_W1[((size_t)h * HDq + e) * (3 * HDq) + c];
        W2s[c * 68 + e] = fu_W2[((size_t)h * HDq + e) * HDq + c];
    }
    __syncthreads();

    float bi[4];
#pragma unroll
    for (int i = 0; i < 4; i++) bi[i] = g_beff[(h * 2 + b) * HDq + tc + i];

    float acc[8][4];
#pragma unroll
    for (int j = 0; j < 8; j++)
#pragma unroll
        for (int i = 0; i < 4; i++) acc[j][i] = bi[i];

#pragma unroll
    for (int k = 0; k < 64; k++) {
        float4 a0 = *(const float4*)&HFs[k * 132 + tr];
        float4 a1 = *(const float4*)&HFs[k * 132 + tr + 4];
        float4 w  = *(const float4*)&W1s[k * 68 + tc];
        float a[8] = {a0.x, a0.y, a0.z, a0.w, a1.x, a1.y, a1.z, a1.w};
        float ww[4] = {w.x, w.y, w.z, w.w};
#pragma unroll
        for (int j = 0; j < 8; j++)
#pragma unroll
            for (int i = 0; i < 4; i++)
                acc[j][i] = fmaf(a[j], ww[i], acc[j][i]);
    }
    __syncthreads();

    // GELU -> reuse HFs as X^T [e][r]
#pragma unroll
    for (int j = 0; j < 8; j++)
#pragma unroll
        for (int i = 0; i < 4; i++) {
            float x = acc[j][i];
            float g = 0.5f * x * (1.0f + erff(x * 0.70710678118654752f));
            HFs[(tc + i) * 132 + (tr + j)] = g;
        }
    __syncthreads();

    float b2r[4];
#pragma unroll
    for (int i = 0; i < 4; i++) b2r[i] = fu_b2[h * HDq + tc + i];

    float acc2[8][4];
#pragma unroll
    for (int j = 0; j < 8; j++)
#pragma unroll
        for (int i = 0; i < 4; i++) acc2[j][i] = b2r[i];

#pragma unroll
    for (int k = 0; k < 64; k++) {
        float4 a0 = *(const float4*)&HFs[k * 132 + tr];
        float4 a1 = *(const float4*)&HFs[k * 132 + tr + 4];
        float4 w  = *(const float4*)&W2s[k * 68 + tc];
        float a[8] = {a0.x, a0.y, a0.z, a0.w, a1.x, a1.y, a1.z, a1.w};
        float ww[4] = {w.x, w.y, w.z, w.w};
#pragma unroll
        for (int j = 0; j < 8; j++)
#pragma unroll
            for (int i = 0; i < 4; i++)
                acc2[j][i] = fmaf(a[j], ww[i], acc2[j][i]);
    }

    // Store bf16 hi/lo of multi
#pragma unroll
    for (int j = 0; j < 8; j++) {
        size_t off = (rowbase + tr + j) * Dq + h * HDq + tc;
        float y[4] = {acc2[j][0], acc2[j][1], acc2[j][2], acc2[j][3]};
        __nv_bfloat16 hh[4], ll[4];
#pragma unroll
        for (int i = 0; i < 4; i++) {
            hh[i] = __float2bfloat16(y[i]);
            ll[i] = __float2bfloat16(y[i] - __bfloat162float(hh[i]));
        }
        __nv_bfloat162 p;
        p.x = hh[0]; p.y = hh[1]; *(__nv_bfloat162*)&g_mH[off] = p;
        p.x = hh[2]; p.y = hh[3]; *(__nv_bfloat162*)&g_mH[off + 2] = p;
        p.x = ll[0]; p.y = ll[1]; *(__nv_bfloat162*)&g_mL[off] = p;
        p.x = ll[2]; p.y = ll[3]; *(__nv_bfloat162*)&g_mL[off + 2] = p;
    }
}

// ---------------------------------------------------------------------------
// Tail: fwd_targets[0], bwd_targets[0], avg_strength (uniform-softmax collapse)
// ---------------------------------------------------------------------------
__global__ void tail_kernel(const int* __restrict__ prev_idx,
                            const float* __restrict__ chain_ratio,
                            float* __restrict__ out) {
    int idx = blockIdx.x * 256 + threadIdx.x;
    if (idx >= ROWS) return;
    int n = idx & (Nq - 1);

    float cr = *chain_ratio;
    float thr = floorf((float)Nq / (1.0f + expf(-cr)));

    int p = prev_idx[idx];
    p = min(max(p, 0), Nq - 1);

    float ft = ((float)n >= thr) ? (float)p : 511.0f;
    out[OUT_FINAL + idx] = ft;
    out[OUT_FINAL + ROWS + idx] = 511.0f;

    float s = 1.0f - logf(1.0f / (float)Nq + 1e-8f);
    out[OUT_FINAL + 2 * ROWS + idx] = s;
}

// ---------------------------------------------------------------------------
extern "C" void kernel_launch(void* const* d_in, const int* in_sizes, int n_in,
                              void* d_out, int out_size) {
    const float* h_in     = (const float*)d_in[0];
    const int*   prev_idx = (const int*)d_in[1];
    // d_in[2..9] = fw/bw encoder weights: dead (softmax of broadcast scalar
    // logit is uniform), never read.
    const float* Wv    = (const float*)d_in[10];
    const float* fu_W1 = (const float*)d_in[11];
    const float* fu_b1 = (const float*)d_in[12];
    const float* fu_W2 = (const float*)d_in[13];
    const float* fu_b2 = (const float*)d_in[14];
    const float* Wo    = (const float*)d_in[15];
    const float* chain_ratio = (const float*)d_in[16];
    float* out = (float*)d_out;

    cudaFuncSetAttribute(gemm_hmma, cudaFuncAttributeMaxDynamicSharedMemorySize, G_SMEM);
    cudaFuncSetAttribute(fusion_kernel, cudaFuncAttributeMaxDynamicSharedMemorySize, F_SMEM);

    float* hf;  cudaGetSymbolAddress((void**)&hf, g_hf);
    __nv_bfloat16 *Ah, *Al, *WvH, *WvL, *WoH, *WoL, *mH, *mL;
    cudaGetSymbolAddress((void**)&Ah,  g_Ah);
    cudaGetSymbolAddress((void**)&Al,  g_Al);
    cudaGetSymbolAddress((void**)&WvH, g_WvH);
    cudaGetSymbolAddress((void**)&WvL, g_WvL);
    cudaGetSymbolAddress((void**)&WoH, g_WoH);
    cudaGetSymbolAddress((void**)&WoL, g_WoL);
    cudaGetSymbolAddress((void**)&mH,  g_mH);
    cudaGetSymbolAddress((void**)&mL,  g_mL);

    // 1) splits (h conversion also zeroes g_mu)
    cvt_hilo<<<2048, 256>>>((const float4*)h_in, Ah, Al, (ROWS * Dq) / 4, 1);
    cvt_hilo<<<1024, 256>>>((const float4*)Wv, WvH, WvL, (Dq * Dq) / 4, 0);
    cvt_hilo<<<1024, 256>>>((const float4*)Wo, WoH, WoL, (Dq * Dq) / 4, 0);

    // 2) head_features = h @ Wv^T  (HMMA bf16-split, K'=3072)
    gemm_hmma<<<dim3(Dq / 128, ROWS / 128), 256, G_SMEM>>>(Ah, Al, WvH, WvL, hf);

    // 3) column sums -> mu ; effective bias
    mu_sum<<<dim3(16, Bq), 256>>>();
    beff_kernel<<<Hh * Bq, HDq>>>(fu_W1, fu_b1);

    // 4) fusion MLP -> multi (bf16 hi/lo)
    fusion_kernel<<<dim3(ROWS / 128, Hh), 256, F_SMEM>>>(fu_W1, fu_W2, fu_b2);

    // 5) final = multi @ Wo^T
    gemm_hmma<<<dim3(Dq / 128, ROWS / 128), 256, G_SMEM>>>(mH, mL, WoH, WoL, out);

    // 6) targets + strength
    tail_kernel<<<ROWS / 256, 256>>>(prev_idx, chain_ratio, out);
}

// round 6
// speedup vs baseline: 2.9324x; 1.0705x over previous
#include <cuda_runtime.h>
#include <cuda_bf16.h>
#include <math.h>
#include <stdint.h>

// Problem constants
#define Dq   1024
#define Hh   16
#define HDq  64
#define Bq   2
#define Nq   1024
#define ROWS (Bq * Nq)          // 2048
#define OUT_FINAL (ROWS * Dq)   // 2097152

// ---------------------------------------------------------------------------
// Scratch (device globals — no allocation allowed)
// ---------------------------------------------------------------------------
__device__ float g_hf[ROWS * Dq];                 // head_features fp32
__device__ float g_mu[Bq * Dq];                   // column SUMS of g_hf per batch
__device__ float g_beff[Hh * Bq * HDq];
__device__ __nv_bfloat16 g_Ah[ROWS * Dq], g_Al[ROWS * Dq];    // h split
__device__ __nv_bfloat16 g_WvH[Dq * Dq], g_WvL[Dq * Dq];      // Wv split
__device__ __nv_bfloat16 g_WoH[Dq * Dq], g_WoL[Dq * Dq];      // Wo split
__device__ __nv_bfloat16 g_mH[ROWS * Dq], g_mL[ROWS * Dq];    // multi split

// ---------------------------------------------------------------------------
// Helpers (base-target instructions only: ldmatrix / mma.sync / cp.async)
// ---------------------------------------------------------------------------
__device__ __forceinline__ uint32_t smem_u32(const void* p) {
    uint32_t a;
    asm("{ .reg .u64 t; cvta.to.shared.u64 t, %1; cvt.u32.u64 %0, t; }"
        : "=r"(a) : "l"(p));
    return a;
}
#define SW128(o) ((o) ^ (((o) >> 3) & 0x70))

#define CP_ASYNC16(dst, src) \
    asm volatile("cp.async.cg.shared.global [%0], [%1], 16;" :: "r"(dst), "l"(src))
#define CP_COMMIT() asm volatile("cp.async.commit_group;")
#define CP_WAIT(n)  asm volatile("cp.async.wait_group %0;" :: "n"(n) : "memory")

__device__ __forceinline__ void ldsm_x4(uint32_t* r, uint32_t addr) {
    asm volatile("ldmatrix.sync.aligned.m8n8.x4.shared.b16 {%0,%1,%2,%3}, [%4];"
                 : "=r"(r[0]), "=r"(r[1]), "=r"(r[2]), "=r"(r[3]) : "r"(addr));
}

__device__ __forceinline__ void mma16816(float* c, const uint32_t* a, const uint32_t* b) {
    asm volatile(
        "mma.sync.aligned.m16n8k16.row.col.f32.bf16.bf16.f32 "
        "{%0,%1,%2,%3}, {%4,%5,%6,%7}, {%8,%9}, {%0,%1,%2,%3};"
        : "+f"(c[0]), "+f"(c[1]), "+f"(c[2]), "+f"(c[3])
        : "r"(a[0]), "r"(a[1]), "r"(a[2]), "r"(a[3]), "r"(b[0]), "r"(b[1]));
}

__device__ __forceinline__ void split4(float4 v, __nv_bfloat16* hi, __nv_bfloat16* lo,
                                       size_t i2) {
    __nv_bfloat16 h0 = __float2bfloat16(v.x);
    __nv_bfloat16 h1 = __float2bfloat16(v.y);
    __nv_bfloat16 h2 = __float2bfloat16(v.z);
    __nv_bfloat16 h3 = __float2bfloat16(v.w);
    __nv_bfloat16 l0 = __float2bfloat16(v.x - __bfloat162float(h0));
    __nv_bfloat16 l1 = __float2bfloat16(v.y - __bfloat162float(h1));
    __nv_bfloat16 l2 = __float2bfloat16(v.z - __bfloat162float(h2));
    __nv_bfloat16 l3 = __float2bfloat16(v.w - __bfloat162float(h3));
    __nv_bfloat162 p;
    p.x = h0; p.y = h1; ((__nv_bfloat162*)hi)[i2] = p;
    p.x = h2; p.y = h3; ((__nv_bfloat162*)hi)[i2 + 1] = p;
    p.x = l0; p.y = l1; ((__nv_bfloat162*)lo)[i2] = p;
    p.x = l2; p.y = l3; ((__nv_bfloat162*)lo)[i2 + 1] = p;
}

// ---------------------------------------------------------------------------
// Fused prologue: hi/lo splits of h, Wv, Wo; zero g_mu; tail outputs.
// grid = 4104 blocks x 256 threads.
//   [0,2048)    : split h (also zero g_mu)
//   [2048,3072) : split Wv
//   [3072,4096) : split Wo
//   [4096,4104) : tail (targets + strength)
// ---------------------------------------------------------------------------
__global__ void __launch_bounds__(256)
cvt_all(const float4* __restrict__ hx, const float4* __restrict__ wv,
        const float4* __restrict__ wo, const int* __restrict__ prev_idx,
        const float* __restrict__ chain_ratio, float* __restrict__ out) {
    int blk = blockIdx.x, tid = threadIdx.x;
    if (blk < 2048) {
        int i = blk * 256 + tid;
        if (i < (Bq * Dq) / 4) ((float4*)g_mu)[i] = make_float4(0.f, 0.f, 0.f, 0.f);
        split4(hx[i], g_Ah, g_Al, (size_t)i * 2);
    } else if (blk < 3072) {
        int i = (blk - 2048) * 256 + tid;
        split4(wv[i], g_WvH, g_WvL, (size_t)i * 2);
    } else if (blk < 4096) {
        int i = (blk - 3072) * 256 + tid;
        split4(wo[i], g_WoH, g_WoL, (size_t)i * 2);
    } else {
        int idx = (blk - 4096) * 256 + tid;
        if (idx >= ROWS) return;
        int n = idx & (Nq - 1);
        float cr = *chain_ratio;
        float thr = floorf((float)Nq / (1.0f + expf(-cr)));
        int p = prev_idx[idx];
        p = min(max(p, 0), Nq - 1);
        float ft = ((float)n >= thr) ? (float)p : 511.0f;
        out[OUT_FINAL + idx] = ft;
        out[OUT_FINAL + ROWS + idx] = 511.0f;
        out[OUT_FINAL + 2 * ROWS + idx] = 1.0f - logf(1.0f / (float)Nq + 1e-8f);
    }
}

// ---------------------------------------------------------------------------
// HMMA bf16 split GEMM: C[2048,1024] f32 = (Ah+Al) @ (Bh+Bl)^T
// Folded K'=3072 over segments (Ah,Bh),(Al,Bh),(Ah,Bl).
// Tile 128x128, BK=64 (128B rows, SW128). 256 thr, 8 warps (4m x 2n).
// 4-stage cp.async pipeline, wait_group 2 (3 tiles / 96KB in flight).
// Optional epilogue: per-batch column sums -> mu (atomicAdd).
// ---------------------------------------------------------------------------
#define G_STAGE 32768            // A 16KB + B 16KB
#define G_SMEM  (4 * G_STAGE)    // 128KB
#define NKT 48

__device__ __forceinline__ void load_tile(uint32_t stage,
                                          const __nv_bfloat16* __restrict__ Aseg,
                                          const __nv_bfloat16* __restrict__ Bseg,
                                          int bm, int bn, int kin, int tid) {
#pragma unroll
    for (int rep = 0; rep < 4; rep++) {
        int id = rep * 256 + tid;        // 0..1023
        int row = id >> 3, c = id & 7;   // 128 rows x 8 chunks of 16B
        uint32_t so = SW128((uint32_t)(row * 128 + c * 16));
        CP_ASYNC16(stage + so, Aseg + (size_t)(bm + row) * Dq + kin + c * 8);
        CP_ASYNC16(stage + 16384 + so, Bseg + (size_t)(bn + row) * Dq + kin + c * 8);
    }
}

__global__ void __launch_bounds__(256, 1)
gemm_hmma(const __nv_bfloat16* __restrict__ Ah, const __nv_bfloat16* __restrict__ Al,
          const __nv_bfloat16* __restrict__ Bh, const __nv_bfloat16* __restrict__ Bl,
          float* __restrict__ C, float* __restrict__ mu) {
    extern __shared__ char sm[];
    const uint32_t smb = smem_u32(sm);
    const int tid = threadIdx.x;
    const int warp = tid >> 5, lane = tid & 31;
    const int wm = warp >> 1, wn = warp & 1;
    const int bm = blockIdx.y * 128, bn = blockIdx.x * 128;

    const __nv_bfloat16* Asegs[3] = {Ah, Al, Ah};
    const __nv_bfloat16* Bsegs[3] = {Bh, Bh, Bl};

    float acc[2][8][4];
#pragma unroll
    for (int mt = 0; mt < 2; mt++)
#pragma unroll
        for (int nt = 0; nt < 8; nt++)
#pragma unroll
            for (int i = 0; i < 4; i++) acc[mt][nt][i] = 0.0f;

    uint32_t a_off[2], b_off[4];
#pragma unroll
    for (int mt = 0; mt < 2; mt++) {
        int row = wm * 32 + mt * 16 + (lane & 15);
        a_off[mt] = (uint32_t)(row * 128 + (lane >> 4) * 16);
    }
#pragma unroll
    for (int np = 0; np < 4; np++) {
        int n = wn * 64 + np * 16 + (lane >> 4) * 8 + (lane & 7);
        b_off[np] = (uint32_t)(n * 128 + ((lane >> 3) & 1) * 16);
    }

    // Prologue: fill 3 stages
#pragma unroll
    for (int s = 0; s < 3; s++) {
        load_tile(smb + s * G_STAGE, Asegs[s >> 4], Bsegs[s >> 4], bm, bn, (s & 15) * 64, tid);
        CP_COMMIT();
    }

    for (int kt = 0; kt < NKT; kt++) {
        CP_WAIT(2);
        __syncthreads();
        // prefetch stage kt+3 (into slot (kt-1)%4, safe after barrier)
        if (kt + 3 < NKT) {
            int pk = kt + 3;
            load_tile(smb + (pk & 3) * G_STAGE, Asegs[pk >> 4], Bsegs[pk >> 4],
                      bm, bn, (pk & 15) * 64, tid);
        }
        CP_COMMIT();

        const uint32_t sA = smb + (kt & 3) * G_STAGE;
        const uint32_t sB = sA + 16384;
#pragma unroll
        for (int ks = 0; ks < 4; ks++) {
            uint32_t af[2][4], bf[8][2];
#pragma unroll
            for (int mt = 0; mt < 2; mt++)
                ldsm_x4(af[mt], sA + SW128(a_off[mt] + ks * 32));
#pragma unroll
            for (int np = 0; np < 4; np++) {
                uint32_t r[4];
                ldsm_x4(r, sB + SW128(b_off[np] + ks * 32));
                bf[np * 2][0] = r[0]; bf[np * 2][1] = r[1];
                bf[np * 2 + 1][0] = r[2]; bf[np * 2 + 1][1] = r[3];
            }
#pragma unroll
            for (int mt = 0; mt < 2; mt++)
#pragma unroll
                for (int nt = 0; nt < 8; nt++)
                    mma16816(acc[mt][nt], af[mt], bf[nt]);
        }
    }

    // Epilogue: direct f32 stores
#pragma unroll
    for (int mt = 0; mt < 2; mt++) {
        int row = bm + wm * 32 + mt * 16 + (lane >> 2);
#pragma unroll
        for (int nt = 0; nt < 8; nt++) {
            int col = bn + wn * 64 + nt * 8 + (lane & 3) * 2;
            *(float2*)&C[(size_t)row * Dq + col] =
                make_float2(acc[mt][nt][0], acc[mt][nt][1]);
            *(float2*)&C[(size_t)(row + 8) * Dq + col] =
                make_float2(acc[mt][nt][2], acc[mt][nt][3]);
        }
    }

    // Optional: per-batch column sums of this C tile -> mu
    if (mu) {
        const int b = bm >> 10;   // 128-row tile lies in one batch
#pragma unroll
        for (int nt = 0; nt < 8; nt++) {
            float s0 = acc[0][nt][0] + acc[0][nt][2] + acc[1][nt][0] + acc[1][nt][2];
            float s1 = acc[0][nt][1] + acc[0][nt][3] + acc[1][nt][1] + acc[1][nt][3];
            s0 += __shfl_down_sync(0xFFFFFFFFu, s0, 16);
            s0 += __shfl_down_sync(0xFFFFFFFFu, s0, 8);
            s0 += __shfl_down_sync(0xFFFFFFFFu, s0, 4);
            s1 += __shfl_down_sync(0xFFFFFFFFu, s1, 16);
            s1 += __shfl_down_sync(0xFFFFFFFFu, s1, 8);
            s1 += __shfl_down_sync(0xFFFFFFFFu, s1, 4);
            if ((lane >> 2) == 0) {
                int col = bn + wn * 64 + nt * 8 + (lane & 3) * 2;
                atomicAdd(&mu[b * Dq + col], s0);
                atomicAdd(&mu[b * Dq + col + 1], s1);
            }
        }
    }
}

// ---------------------------------------------------------------------------
// Effective bias: beff[h,b,e] = fu_b1[h,e] + sum_e' (W1b+W1c)[h,e,e'] * mu/N
// ---------------------------------------------------------------------------
__global__ void beff_kernel(const float* __restrict__ fu_W1,
                            const float* __restrict__ fu_b1) {
    int hb = blockIdx.x;            // 0..31
    int h = hb >> 1, b = hb & 1;
    int e = threadIdx.x;            // 0..63
    const float* w = fu_W1 + (size_t)h * HDq * 3 * HDq + (size_t)e * 3 * HDq;
    const float* mu = g_mu + b * Dq + h * HDq;
    float acc = fu_b1[h * HDq + e];
    const float inv = 1.0f / (float)Nq;
#pragma unroll 8
    for (int ep = 0; ep < HDq; ep++)
        acc = fmaf(w[HDq + ep] + w[2 * HDq + ep], mu[ep] * inv, acc);
    g_beff[hb * HDq + e] = acc;
}

// ---------------------------------------------------------------------------
// Fusion MLP, register-tiled. 128 rows x 64 cols per (rowchunk, head).
// Grid (16, 16), 256 threads, TM=8 x TN=4. Outputs multi as bf16 hi/lo.
// ---------------------------------------------------------------------------
#define F_HFS 0
#define F_W1S (64 * 132)
#define F_W2S (64 * 132 + 64 * 68)
#define F_SMEM ((64 * 132 + 2 * 64 * 68) * 4)

__global__ void __launch_bounds__(256)
fusion_kernel(const float* __restrict__ fu_W1, const float* __restrict__ fu_W2,
              const float* __restrict__ fu_b2) {
    extern __shared__ float fsm[];
    float* HFs = fsm + F_HFS;
    float* W1s = fsm + F_W1S;
    float* W2s = fsm + F_W2S;

    const int rc = blockIdx.x, h = blockIdx.y;
    const int b = rc >> 3;
    const int tid = threadIdx.x;
    const int tr = (tid >> 4) * 8;
    const int tc = (tid & 15) * 4;
    const size_t rowbase = (size_t)rc * 128;

#pragma unroll
    for (int rep = 0; rep < 8; rep++) {
        int e = rep * 256 + tid;
        int r = e >> 4, c4 = (e & 15) * 4;
        float4 v = *(const float4*)&g_hf[(rowbase + r) * Dq + h * HDq + c4];
        HFs[(c4 + 0) * 132 + r] = v.x;
        HFs[(c4 + 1) * 132 + r] = v.y;
        HFs[(c4 + 2) * 132 + r] = v.z;
        HFs[(c4 + 3) * 132 + r] = v.w;
    }
#pragma unroll
    for (int rep = 0; rep < 16; rep++) {
        int idx = rep * 256 + tid;
        int e = idx >> 6, c = idx & 63;
        W1s[c * 68 + e] = fu_W1[((size_t)h * HDq + e) * (3 * HDq) + c];
        W2s[c * 68 + e] = fu_W2[((size_t)h * HDq + e) * HDq + c];
    }
    __syncthreads();

    float bi[4];
#pragma unroll
    for (int i = 0; i < 4; i++) bi[i] = g_beff[(h * 2 + b) * HDq + tc + i];

    float acc[8][4];
#pragma unroll
    for (int j = 0; j < 8; j++)
#pragma unroll
        for (int i = 0; i < 4; i++) acc[j][i] = bi[i];

#pragma unroll
    for (int k = 0; k < 64; k++) {
        float4 a0 = *(const float4*)&HFs[k * 132 + tr];
        float4 a1 = *(const float4*)&HFs[k * 132 + tr + 4];
        float4 w  = *(const float4*)&W1s[k * 68 + tc];
        float a[8] = {a0.x, a0.y, a0.z, a0.w, a1.x, a1.y, a1.z, a1.w};
        float ww[4] = {w.x, w.y, w.z, w.w};
#pragma unroll
        for (int j = 0; j < 8; j++)
#pragma unroll
            for (int i = 0; i < 4; i++)
                acc[j][i] = fmaf(a[j], ww[i], acc[j][i]);
    }
    __syncthreads();

#pragma unroll
    for (int j = 0; j < 8; j++)
#pragma unroll
        for (int i = 0; i < 4; i++) {
            float x = acc[j][i];
            float g = 0.5f * x * (1.0f + erff(x * 0.70710678118654752f));
            HFs[(tc + i) * 132 + (tr + j)] = g;
        }
    __syncthreads();

    float b2r[4];
#pragma unroll
    for (int i = 0; i < 4; i++) b2r[i] = fu_b2[h * HDq + tc + i];

    float acc2[8][4];
#pragma unroll
    for (int j = 0; j < 8; j++)
#pragma unroll
        for (int i = 0; i < 4; i++) acc2[j][i] = b2r[i];

#pragma unroll
    for (int k = 0; k < 64; k++) {
        float4 a0 = *(const float4*)&HFs[k * 132 + tr];
        float4 a1 = *(const float4*)&HFs[k * 132 + tr + 4];
        float4 w  = *(const float4*)&W2s[k * 68 + tc];
        float a[8] = {a0.x, a0.y, a0.z, a0.w, a1.x, a1.y, a1.z, a1.w};
        float ww[4] = {w.x, w.y, w.z, w.w};
#pragma unroll
        for (int j = 0; j < 8; j++)
#pragma unroll
            for (int i = 0; i < 4; i++)
                acc2[j][i] = fmaf(a[j], ww[i], acc2[j][i]);
    }

#pragma unroll
    for (int j = 0; j < 8; j++) {
        size_t off = (rowbase + tr + j) * Dq + h * HDq + tc;
        float4 y = make_float4(acc2[j][0], acc2[j][1], acc2[j][2], acc2[j][3]);
        split4(y, g_mH, g_mL, off >> 1);
    }
}

// ---------------------------------------------------------------------------
extern "C" void kernel_launch(void* const* d_in, const int* in_sizes, int n_in,
                              void* d_out, int out_size) {
    const float* h_in     = (const float*)d_in[0];
    const int*   prev_idx = (const int*)d_in[1];
    // d_in[2..9] = fw/bw encoder weights: dead (softmax of broadcast scalar
    // logit is uniform), never read.
    const float* Wv    = (const float*)d_in[10];
    const float* fu_W1 = (const float*)d_in[11];
    const float* fu_b1 = (const float*)d_in[12];
    const float* fu_W2 = (const float*)d_in[13];
    const float* fu_b2 = (const float*)d_in[14];
    const float* Wo    = (const float*)d_in[15];
    const float* chain_ratio = (const float*)d_in[16];
    float* out = (float*)d_out;

    cudaFuncSetAttribute(gemm_hmma, cudaFuncAttributeMaxDynamicSharedMemorySize, G_SMEM);
    cudaFuncSetAttribute(fusion_kernel, cudaFuncAttributeMaxDynamicSharedMemorySize, F_SMEM);

    float* hf;  cudaGetSymbolAddress((void**)&hf, g_hf);
    float* mu;  cudaGetSymbolAddress((void**)&mu, g_mu);
    __nv_bfloat16 *Ah, *Al, *WvH, *WvL, *WoH, *WoL, *mH, *mL;
    cudaGetSymbolAddress((void**)&Ah,  g_Ah);
    cudaGetSymbolAddress((void**)&Al,  g_Al);
    cudaGetSymbolAddress((void**)&WvH, g_WvH);
    cudaGetSymbolAddress((void**)&WvL, g_WvL);
    cudaGetSymbolAddress((void**)&WoH, g_WoH);
    cudaGetSymbolAddress((void**)&WoL, g_WoL);
    cudaGetSymbolAddress((void**)&mH,  g_mH);
    cudaGetSymbolAddress((void**)&mL,  g_mL);

    // 1) fused: splits + zero mu + tail outputs
    cvt_all<<<4104, 256>>>((const float4*)h_in, (const float4*)Wv, (const float4*)Wo,
                           prev_idx, chain_ratio, out);

    // 2) head_features = h @ Wv^T ; epilogue accumulates column sums -> mu
    gemm_hmma<<<dim3(Dq / 128, ROWS / 128), 256, G_SMEM>>>(Ah, Al, WvH, WvL, hf, mu);

    // 3) effective bias
    beff_kernel<<<Hh * Bq, HDq>>>(fu_W1, fu_b1);

    // 4) fusion MLP -> multi (bf16 hi/lo)
    fusion_kernel<<<dim3(ROWS / 128, Hh), 256, F_SMEM>>>(fu_W1, fu_W2, fu_b2);

    // 5) final = multi @ Wo^T
    gemm_hmma<<<dim3(Dq / 128, ROWS / 128), 256, G_SMEM>>>(mH, mL, WoH, WoL, out, nullptr);
}